// round 1
// baseline (speedup 1.0000x reference)
#include <cuda_runtime.h>

#define BB 32
#define TT 1024
#define NN 128
#define RBLK 4                       // row blocks per batch
#define ROWS_PER_CTA (NN / RBLK)     // 32
#define THREADS 256
#define LANES_PER_ROW (THREADS / ROWS_PER_CTA)  // 8
#define COLS_PER_LANE (NN / LANES_PER_ROW)      // 16
#define CHUNK 32
#define NCHUNK (TT / CHUNK)          // 32

// ---------- packed f32x2 helpers ----------
__device__ __forceinline__ unsigned long long pack2(float lo, float hi) {
    unsigned long long r;
    asm("mov.b64 %0, {%1, %2};" : "=l"(r) : "f"(lo), "f"(hi));
    return r;
}
__device__ __forceinline__ void unpack2(unsigned long long v, float& lo, float& hi) {
    asm("mov.b64 {%0, %1}, %2;" : "=f"(lo), "=f"(hi) : "l"(v));
}
__device__ __forceinline__ unsigned long long fma2(unsigned long long a,
                                                   unsigned long long b,
                                                   unsigned long long c) {
    unsigned long long d;
    asm("fma.rn.f32x2 %0, %1, %2, %3;" : "=l"(d) : "l"(a), "l"(b), "l"(c));
    return d;
}
__device__ __forceinline__ unsigned long long mul2(unsigned long long a,
                                                   unsigned long long b) {
    unsigned long long d;
    asm("mul.rn.f32x2 %0, %1, %2;" : "=l"(d) : "l"(a), "l"(b));
    return d;
}

// ---------- cp.async helpers ----------
__device__ __forceinline__ void cpasync16(void* s, const void* g) {
    unsigned saddr = (unsigned)__cvta_generic_to_shared(s);
    asm volatile("cp.async.cg.shared.global [%0], [%1], 16;" :: "r"(saddr), "l"(g));
}
__device__ __forceinline__ void load_chunk(float* dst, const float* src, int tid) {
    #pragma unroll
    for (int i = 0; i < 4; i++) {
        int off = (tid + i * THREADS) * 4;   // in floats, 16B per thread per iter
        cpasync16(dst + off, src + off);
    }
}

__global__ __launch_bounds__(THREADS, 1)
void bdh_scan_kernel(const float* __restrict__ x,
                     const float* __restrict__ w_init,
                     const float* __restrict__ alpha_p,
                     const float* __restrict__ eta_p,
                     const int*   __restrict__ mask,
                     float* __restrict__ w_out,
                     float* __restrict__ y_out)
{
    __shared__ float xs[2][CHUNK * NN];  // 2 x 16 KB double buffer
    __shared__ int   ms[TT];             // full mask row for this batch (4 KB)

    const int b   = blockIdx.x;
    const int rb  = blockIdx.y;
    const int tid = threadIdx.x;
    const int rloc = tid / LANES_PER_ROW;                  // 0..31
    const int r    = rb * ROWS_PER_CTA + rloc;             // global row in [0,128)
    const int cseg = (tid % LANES_PER_ROW) * COLS_PER_LANE; // column start

    const float alpha = alpha_p[0];
    const float eta   = eta_p[0];
    const float inva  = 1.0f / alpha;

    // ---- load W rows into registers (8 packed f32x2 = 16 floats) ----
    unsigned long long w2[8];
    {
        const ulonglong2* wsrc = reinterpret_cast<const ulonglong2*>(
            w_init + (size_t)b * NN * NN + (size_t)r * NN + cseg);
        #pragma unroll
        for (int i = 0; i < 4; i++) {
            ulonglong2 v = wsrc[i];
            w2[2 * i]     = v.x;
            w2[2 * i + 1] = v.y;
        }
    }

    // ---- preload mask for this batch ----
    for (int i = tid; i < TT; i += THREADS) ms[i] = mask[(size_t)b * TT + i];

    const float* xb = x + (size_t)b * TT * NN;
    float* yb = y_out + (size_t)b * TT * NN;

    // ---- prologue: prefetch first two chunks ----
    load_chunk(xs[0], xb, tid);
    asm volatile("cp.async.commit_group;");
    load_chunk(xs[1], xb + CHUNK * NN, tid);
    asm volatile("cp.async.commit_group;");

    float c = 1.0f;   // W = c * U  (deferred decay scale)
    float ic = 1.0f;  // 1/c

    for (int ck = 0; ck < NCHUNK; ck++) {
        asm volatile("cp.async.wait_group 1;");
        __syncthreads();
        const float* xchunk = xs[ck & 1];

        #pragma unroll 4
        for (int tl = 0; tl < CHUNK; tl++) {
            const float* xp = xchunk + tl * NN;

            // load this lane's 16 x values (broadcast-friendly across rows)
            unsigned long long xv[8];
            #pragma unroll
            for (int i = 0; i < 4; i++) {
                ulonglong2 v = reinterpret_cast<const ulonglong2*>(xp + cseg)[i];
                xv[2 * i]     = v.x;
                xv[2 * i + 1] = v.y;
            }

            // partial dot: p = U[r, cseg:cseg+16] . x
            unsigned long long a0 = 0ull, a1 = 0ull;
            #pragma unroll
            for (int k = 0; k < 8; k += 2) {
                a0 = fma2(w2[k],     xv[k],     a0);
                a1 = fma2(w2[k + 1], xv[k + 1], a1);
            }
            float l0, h0, l1, h1;
            unpack2(a0, l0, h0);
            unpack2(a1, l1, h1);
            float p = (l0 + h0) + (l1 + h1);

            // reduce across the 8 lanes of this row (contiguous lanes)
            p += __shfl_xor_sync(0xffffffffu, p, 4);
            p += __shfl_xor_sync(0xffffffffu, p, 2);
            p += __shfl_xor_sync(0xffffffffu, p, 1);

            const int t = ck * CHUNK + tl;
            if ((tid & (LANES_PER_ROW - 1)) == 0)
                yb[(size_t)t * NN + r] = p * c;   // y uses PRE-update W = c*U

            // masked Hebbian update (branch is uniform across the block)
            if (ms[t]) {
                c  *= alpha;
                ic *= inva;
                const float xr = xp[r];
                const float g  = (eta * ic) * xr;   // eta/c' * x_r
                const unsigned long long g2 = pack2(g, g);
                #pragma unroll
                for (int k = 0; k < 8; k++)
                    w2[k] = fma2(g2, xv[k], w2[k]); // single FMA per element
            }
        }

        // fold accumulated decay back into U once per chunk (alpha^-32 ~ 29, safe)
        if (c != 1.0f) {
            const unsigned long long c2 = pack2(c, c);
            #pragma unroll
            for (int k = 0; k < 8; k++) w2[k] = mul2(w2[k], c2);
            c = 1.0f;
            ic = 1.0f;
        }

        __syncthreads();  // everyone done reading buffer (ck&1) before refill
        const int nk = ck + 2;
        if (nk < NCHUNK)
            load_chunk(xs[ck & 1], xb + (size_t)nk * CHUNK * NN, tid);
        asm volatile("cp.async.commit_group;");  // always commit (possibly empty)
    }

    // ---- write w_final (c == 1 after last renorm) ----
    {
        ulonglong2* wdst = reinterpret_cast<ulonglong2*>(
            w_out + (size_t)b * NN * NN + (size_t)r * NN + cseg);
        #pragma unroll
        for (int i = 0; i < 4; i++) {
            ulonglong2 v;
            v.x = w2[2 * i];
            v.y = w2[2 * i + 1];
            wdst[i] = v;
        }
    }
}

extern "C" void kernel_launch(void* const* d_in, const int* in_sizes, int n_in,
                              void* d_out, int out_size) {
    const float* x      = (const float*)d_in[0];
    const float* w_init = (const float*)d_in[1];
    const float* alpha  = (const float*)d_in[2];
    const float* eta    = (const float*)d_in[3];
    const int*   mask   = (const int*)d_in[4];

    float* w_out = (float*)d_out;                              // [B,N,N] first
    float* y_out = (float*)d_out + (size_t)BB * NN * NN;       // then [B,T,N]

    dim3 grid(BB, RBLK);
    bdh_scan_kernel<<<grid, THREADS>>>(x, w_init, alpha, eta, mask,
                                       w_out, y_out);
}

// round 2
// speedup vs baseline: 1.8301x; 1.8301x over previous
#include <cuda_runtime.h>

#define BB 32
#define TT 1024
#define NN 128
#define RBLK 4                         // row-blocks per batch -> 128 CTAs
#define ROWS 32                        // rows per CTA
#define THREADS 512
#define LANES 16                       // lanes per row
#define CPT 8                          // cols per thread (16 lanes * 8 = 128)
#define CHUNK 32
#define NCHUNK (TT / CHUNK)
#define PBS 17                         // padded lane stride (bank-conflict-free)

// dynamic smem layout (floats):
//   xs[2][CHUNK*NN]            : 8192
//   pbuf[CHUNK][ROWS][PBS]     : 17408
//   cs[CHUNK]                  : 32
//   mbits[NCHUNK] (as uint)    : 32
#define SM_XS     0
#define SM_PBUF   (2 * CHUNK * NN)
#define SM_CS     (SM_PBUF + CHUNK * ROWS * PBS)
#define SM_MBITS  (SM_CS + CHUNK)
#define SM_FLOATS (SM_MBITS + NCHUNK)
#define SM_BYTES  (SM_FLOATS * 4)

// ---------- packed f32x2 helpers ----------
__device__ __forceinline__ unsigned long long pack2(float lo, float hi) {
    unsigned long long r;
    asm("mov.b64 %0, {%1, %2};" : "=l"(r) : "f"(lo), "f"(hi));
    return r;
}
__device__ __forceinline__ void unpack2(unsigned long long v, float& lo, float& hi) {
    asm("mov.b64 {%0, %1}, %2;" : "=f"(lo), "=f"(hi) : "l"(v));
}
__device__ __forceinline__ unsigned long long fma2(unsigned long long a,
                                                   unsigned long long b,
                                                   unsigned long long c) {
    unsigned long long d;
    asm("fma.rn.f32x2 %0, %1, %2, %3;" : "=l"(d) : "l"(a), "l"(b), "l"(c));
    return d;
}
__device__ __forceinline__ unsigned long long mul2(unsigned long long a,
                                                   unsigned long long b) {
    unsigned long long d;
    asm("mul.rn.f32x2 %0, %1, %2;" : "=l"(d) : "l"(a), "l"(b));
    return d;
}

// ---------- cp.async helpers ----------
__device__ __forceinline__ void cpasync16(void* s, const void* g) {
    unsigned saddr = (unsigned)__cvta_generic_to_shared(s);
    asm volatile("cp.async.cg.shared.global [%0], [%1], 16;" :: "r"(saddr), "l"(g));
}
// 4096 floats per chunk, 512 threads * 8 floats each (2x16B, contiguous per thread)
__device__ __forceinline__ void load_chunk(float* dst, const float* src, int tid) {
    cpasync16(dst + tid * 8,     src + tid * 8);
    cpasync16(dst + tid * 8 + 4, src + tid * 8 + 4);
}

__global__ __launch_bounds__(THREADS, 1)
void bdh_scan_kernel(const float* __restrict__ x,
                     const float* __restrict__ w_init,
                     const float* __restrict__ alpha_p,
                     const float* __restrict__ eta_p,
                     const int*   __restrict__ mask,
                     float* __restrict__ w_out,
                     float* __restrict__ y_out)
{
    extern __shared__ float smem[];
    float*    xs    = smem + SM_XS;
    float*    pbuf  = smem + SM_PBUF;
    float*    cs    = smem + SM_CS;
    unsigned* mbits = (unsigned*)(smem + SM_MBITS);

    const int b    = blockIdx.x;
    const int rb   = blockIdx.y;
    const int tid  = threadIdx.x;
    const int rloc = tid / LANES;                 // 0..31
    const int r    = rb * ROWS + rloc;            // global row / output col
    const int lane = tid % LANES;
    const int cseg = lane * CPT;                  // column start

    const float alpha = alpha_p[0];
    const float eta   = eta_p[0];
    const float inva  = 1.0f / alpha;

    // ---- W rows: 8 floats = 4 packed f32x2 in registers ----
    unsigned long long w2[4];
    {
        const ulonglong2* ws = reinterpret_cast<const ulonglong2*>(
            w_init + (size_t)b * NN * NN + (size_t)r * NN + cseg);
        ulonglong2 v0 = ws[0], v1 = ws[1];
        w2[0] = v0.x; w2[1] = v0.y; w2[2] = v1.x; w2[3] = v1.y;
    }

    // ---- build per-chunk mask bitfields via ballot (once) ----
    {
        const int l32 = tid & 31, wi = tid >> 5;   // 16 warps cover 32 chunks
        #pragma unroll
        for (int q = 0; q < 2; q++) {
            const int ckk = wi + q * 16;
            int m = mask[(size_t)b * TT + ckk * 32 + l32];
            unsigned bits = __ballot_sync(0xffffffffu, m != 0);
            if (l32 == 0) mbits[ckk] = bits;
        }
    }

    const float* xb = x + (size_t)b * TT * NN;
    float* yb = y_out + (size_t)b * TT * NN;

    // ---- prefetch first two chunks ----
    load_chunk(xs, xb, tid);
    asm volatile("cp.async.commit_group;");
    load_chunk(xs + CHUNK * NN, xb + CHUNK * NN, tid);
    asm volatile("cp.async.commit_group;");

    float c = 1.0f;    // deferred decay: W = c * U
    float ic = 1.0f;   // 1/c

    float* ppbase = pbuf + rloc * PBS + lane;

    for (int ck = 0; ck < NCHUNK; ck++) {
        asm volatile("cp.async.wait_group 1;");
        __syncthreads();   // x chunk ready; prev reduction done reading pbuf

        const float* xch = xs + (ck & 1) * (CHUNK * NN);
        const unsigned mb = mbits[ck];

        #pragma unroll
        for (int tl = 0; tl < CHUNK; tl++) {
            const float* xp = xch + tl * NN;

            ulonglong2 v0 = reinterpret_cast<const ulonglong2*>(xp + cseg)[0];
            ulonglong2 v1 = reinterpret_cast<const ulonglong2*>(xp + cseg)[1];

            // partial dot over 8 cols (packed)
            unsigned long long a = mul2(w2[0], v0.x);
            a = fma2(w2[1], v0.y, a);
            a = fma2(w2[2], v1.x, a);
            a = fma2(w2[3], v1.y, a);
            float lo, hi;
            unpack2(a, lo, hi);
            ppbase[tl * (ROWS * PBS)] = lo + hi;     // deferred reduction

            if (tid == 0) cs[tl] = c;                // scale for y at step t

            if ((mb >> tl) & 1u) {                   // uniform branch
                c  *= alpha;
                ic *= inva;
                const float g = (eta * ic) * xp[r];
                const unsigned long long g2 = pack2(g, g);
                w2[0] = fma2(g2, v0.x, w2[0]);
                w2[1] = fma2(g2, v0.y, w2[1]);
                w2[2] = fma2(g2, v1.x, w2[2]);
                w2[3] = fma2(g2, v1.y, w2[3]);
            }
        }

        // fold decay back into U once per chunk (alpha^-32 ~ 29, safe range)
        if (c != 1.0f) {
            const unsigned long long c2 = pack2(c, c);
            #pragma unroll
            for (int k = 0; k < 4; k++) w2[k] = mul2(w2[k], c2);
            c = 1.0f; ic = 1.0f;
        }

        __syncthreads();   // partials + cs visible; x buffer free for refill

        const int nk = ck + 2;
        if (nk < NCHUNK)
            load_chunk(xs + (ck & 1) * (CHUNK * NN), xb + (size_t)nk * CHUNK * NN, tid);
        asm volatile("cp.async.commit_group;");

        // ---- bulk reduction: 1024 outputs, 2 per thread, coalesced y stores ----
        #pragma unroll
        for (int o = 0; o < 2; o++) {
            const int idx = tid + o * THREADS;
            const int s  = idx >> 5;        // step in chunk
            const int rr = idx & 31;        // local row
            const float* pp = pbuf + s * (ROWS * PBS) + rr * PBS;
            float sum = 0.0f;
            #pragma unroll
            for (int l = 0; l < LANES; l++) sum += pp[l];
            yb[(size_t)(ck * CHUNK + s) * NN + rb * ROWS + rr] = cs[s] * sum;
        }
        // NOTE: next iteration's top __syncthreads orders these reads
        // before pbuf is overwritten.
    }

    // ---- final W (scale folded, c == 1) ----
    {
        ulonglong2* wd = reinterpret_cast<ulonglong2*>(
            w_out + (size_t)b * NN * NN + (size_t)r * NN + cseg);
        ulonglong2 v0, v1;
        v0.x = w2[0]; v0.y = w2[1]; v1.x = w2[2]; v1.y = w2[3];
        wd[0] = v0; wd[1] = v1;
    }
}

extern "C" void kernel_launch(void* const* d_in, const int* in_sizes, int n_in,
                              void* d_out, int out_size) {
    const float* x      = (const float*)d_in[0];
    const float* w_init = (const float*)d_in[1];
    const float* alpha  = (const float*)d_in[2];
    const float* eta    = (const float*)d_in[3];
    const int*   mask   = (const int*)d_in[4];

    float* w_out = (float*)d_out;
    float* y_out = (float*)d_out + (size_t)BB * NN * NN;

    static bool attr_set = false;
    if (!attr_set) {
        cudaFuncSetAttribute(bdh_scan_kernel,
                             cudaFuncAttributeMaxDynamicSharedMemorySize, SM_BYTES);
        attr_set = true;
    }

    dim3 grid(BB, RBLK);
    bdh_scan_kernel<<<grid, THREADS, SM_BYTES>>>(x, w_init, alpha, eta, mask,
                                                 w_out, y_out);
}

// round 3
// speedup vs baseline: 3.2825x; 1.7936x over previous
#include <cuda_runtime.h>

#define BB 32
#define TT 1024
#define NN 128
#define RBLK 4                      // row-blocks per batch -> 128 CTAs
#define ROWS 32                     // rows per CTA
#define THREADS 128
#define TR 4                        // rows per thread
#define TC 8                        // cols per thread
#define LANES 16                    // lane-groups per row (128/TC)
#define QGRP (ROWS / TR)            // 8 row-groups
#define CHUNK 32
#define NCHUNK (TT / CHUNK)
#define PROW 17                     // padded lane stride in pbuf

// smem (floats):
//  xs[2][CHUNK*NN]             8192
//  pbuf[CHUNK][ROWS][PROW]    17408
//  apow[CHUNK+1]                 33
//  mbits[NCHUNK]                 32
#define SM_XS    0
#define SM_PBUF  (2 * CHUNK * NN)
#define SM_APOW  (SM_PBUF + CHUNK * ROWS * PROW)
#define SM_MBITS (SM_APOW + CHUNK + 1)
#define SM_FLOATS (SM_MBITS + NCHUNK)
#define SM_BYTES (SM_FLOATS * 4)

// ---------- packed f32x2 helpers ----------
__device__ __forceinline__ unsigned long long pack2(float lo, float hi) {
    unsigned long long r;
    asm("mov.b64 %0, {%1, %2};" : "=l"(r) : "f"(lo), "f"(hi));
    return r;
}
__device__ __forceinline__ void unpack2(unsigned long long v, float& lo, float& hi) {
    asm("mov.b64 {%0, %1}, %2;" : "=f"(lo), "=f"(hi) : "l"(v));
}
__device__ __forceinline__ unsigned long long fma2(unsigned long long a,
                                                   unsigned long long b,
                                                   unsigned long long c) {
    unsigned long long d;
    asm("fma.rn.f32x2 %0, %1, %2, %3;" : "=l"(d) : "l"(a), "l"(b), "l"(c));
    return d;
}
__device__ __forceinline__ unsigned long long mul2(unsigned long long a,
                                                   unsigned long long b) {
    unsigned long long d;
    asm("mul.rn.f32x2 %0, %1, %2;" : "=l"(d) : "l"(a), "l"(b));
    return d;
}

// ---------- cp.async ----------
__device__ __forceinline__ void cpasync16(void* s, const void* g) {
    unsigned saddr = (unsigned)__cvta_generic_to_shared(s);
    asm volatile("cp.async.cg.shared.global [%0], [%1], 16;" :: "r"(saddr), "l"(g));
}
// 4096 floats / 128 threads = 32 floats = 8 x 16B per thread
__device__ __forceinline__ void load_chunk(float* dst, const float* src, int tid) {
    #pragma unroll
    for (int i = 0; i < 8; i++) {
        int off = (tid + i * THREADS) * 4;
        cpasync16(dst + off, src + off);
    }
}

__global__ __launch_bounds__(THREADS, 1)
void bdh_scan_kernel(const float* __restrict__ x,
                     const float* __restrict__ w_init,
                     const float* __restrict__ alpha_p,
                     const float* __restrict__ eta_p,
                     const int*   __restrict__ mask,
                     float* __restrict__ w_out,
                     float* __restrict__ y_out)
{
    extern __shared__ float smem[];
    float*    xs    = smem + SM_XS;
    float*    pbuf  = smem + SM_PBUF;
    float*    apow  = smem + SM_APOW;
    unsigned* mbits = (unsigned*)(smem + SM_MBITS);

    const int b    = blockIdx.x;
    const int rb   = blockIdx.y;
    const int tid  = threadIdx.x;
    const int q    = tid / LANES;          // 0..7 row-group
    const int lane = tid % LANES;          // 0..15
    const int r0l  = q * TR;               // local first row (0..28)
    const int r0   = rb * ROWS + r0l;      // global first row
    const int cseg = lane * TC;            // col start

    const float alpha = alpha_p[0];
    const float eta   = eta_p[0];
    const float inva  = 1.0f / alpha;

    // ---- W tile: 4 rows x 8 cols = 16 packed f32x2 ----
    unsigned long long w2[TR][4];
    {
        const float* wb = w_init + (size_t)b * NN * NN + (size_t)r0 * NN + cseg;
        #pragma unroll
        for (int i = 0; i < TR; i++) {
            const ulonglong2* ws = reinterpret_cast<const ulonglong2*>(wb + i * NN);
            ulonglong2 v0 = ws[0], v1 = ws[1];
            w2[i][0] = v0.x; w2[i][1] = v0.y; w2[i][2] = v1.x; w2[i][3] = v1.y;
        }
    }

    // ---- mask bitfields: 4 warps x 8 chunks ----
    {
        const int l32 = tid & 31, wi = tid >> 5;
        for (int ckk = wi; ckk < NCHUNK; ckk += 4) {
            int m = mask[(size_t)b * TT + ckk * 32 + l32];
            unsigned bits = __ballot_sync(0xffffffffu, m != 0);
            if (l32 == 0) mbits[ckk] = bits;
        }
    }
    // ---- alpha power table (once) ----
    if (tid == 0) {
        float p = 1.0f;
        #pragma unroll
        for (int k = 0; k <= CHUNK; k++) { apow[k] = p; p *= alpha; }
    }

    const float* xb = x + (size_t)b * TT * NN;
    float* yb = y_out + (size_t)b * TT * NN;

    load_chunk(xs, xb, tid);
    asm volatile("cp.async.commit_group;");
    load_chunk(xs + CHUNK * NN, xb + CHUNK * NN, tid);
    asm volatile("cp.async.commit_group;");

    float c = 1.0f, ic = 1.0f;     // deferred decay: W = c*U

    for (int ck = 0; ck < NCHUNK; ck++) {
        asm volatile("cp.async.wait_group 1;");
        __syncthreads();

        const float* xch = xs + (ck & 1) * (CHUNK * NN);
        const unsigned mb = mbits[ck];

        #pragma unroll 4
        for (int tl = 0; tl < CHUNK; tl++) {
            const float* xp = xch + tl * NN;

            // x columns for this lane (8 floats), reused by 4 rows
            ulonglong2 v0 = reinterpret_cast<const ulonglong2*>(xp + cseg)[0];
            ulonglong2 v1 = reinterpret_cast<const ulonglong2*>(xp + cseg)[1];
            unsigned long long xv0 = v0.x, xv1 = v0.y, xv2 = v1.x, xv3 = v1.y;

            // x rows (4 floats, broadcast) — needed only when masked,
            // but load unconditionally to keep it off the critical path
            float4 xr = *reinterpret_cast<const float4*>(xp + r0l + rb * ROWS);

            // 4 independent dot chains
            float p[TR];
            #pragma unroll
            for (int i = 0; i < TR; i++) {
                unsigned long long a0 = mul2(w2[i][0], xv0);
                unsigned long long a1 = mul2(w2[i][1], xv1);
                a0 = fma2(w2[i][2], xv2, a0);
                a1 = fma2(w2[i][3], xv3, a1);
                float l0, h0, l1, h1;
                unpack2(a0, l0, h0);
                unpack2(a1, l1, h1);
                p[i] = (l0 + h0) + (l1 + h1);
            }
            float* pb = pbuf + tl * (ROWS * PROW) + r0l * PROW + lane;
            pb[0 * PROW] = p[0];
            pb[1 * PROW] = p[1];
            pb[2 * PROW] = p[2];
            pb[3 * PROW] = p[3];

            if ((mb >> tl) & 1u) {          // uniform branch
                c  *= alpha;
                ic *= inva;
                const float s = eta * ic;
                const unsigned long long g0 = pack2(s * xr.x, s * xr.x);
                const unsigned long long g1 = pack2(s * xr.y, s * xr.y);
                const unsigned long long g2 = pack2(s * xr.z, s * xr.z);
                const unsigned long long g3 = pack2(s * xr.w, s * xr.w);
                w2[0][0] = fma2(g0, xv0, w2[0][0]);
                w2[0][1] = fma2(g0, xv1, w2[0][1]);
                w2[0][2] = fma2(g0, xv2, w2[0][2]);
                w2[0][3] = fma2(g0, xv3, w2[0][3]);
                w2[1][0] = fma2(g1, xv0, w2[1][0]);
                w2[1][1] = fma2(g1, xv1, w2[1][1]);
                w2[1][2] = fma2(g1, xv2, w2[1][2]);
                w2[1][3] = fma2(g1, xv3, w2[1][3]);
                w2[2][0] = fma2(g2, xv0, w2[2][0]);
                w2[2][1] = fma2(g2, xv1, w2[2][1]);
                w2[2][2] = fma2(g2, xv2, w2[2][2]);
                w2[2][3] = fma2(g2, xv3, w2[2][3]);
                w2[3][0] = fma2(g3, xv0, w2[3][0]);
                w2[3][1] = fma2(g3, xv1, w2[3][1]);
                w2[3][2] = fma2(g3, xv2, w2[3][2]);
                w2[3][3] = fma2(g3, xv3, w2[3][3]);
            }
        }

        // fold decay into U (alpha^-32 ~ 29, safe)
        if (c != 1.0f) {
            const unsigned long long c2 = pack2(c, c);
            #pragma unroll
            for (int i = 0; i < TR; i++)
                #pragma unroll
                for (int k = 0; k < 4; k++) w2[i][k] = mul2(w2[i][k], c2);
            c = 1.0f; ic = 1.0f;
        }

        __syncthreads();   // partials visible; x buffer free

        const int nk = ck + 2;
        if (nk < NCHUNK)
            load_chunk(xs + (ck & 1) * (CHUNK * NN), xb + (size_t)nk * CHUNK * NN, tid);
        asm volatile("cp.async.commit_group;");

        // ---- bulk reduction: 1024 y per chunk, 8 per thread, coalesced ----
        #pragma unroll
        for (int o = 0; o < 8; o++) {
            const int idx = tid + o * THREADS;
            const int s  = idx >> 5;          // step in chunk
            const int rr = idx & 31;          // local row
            const float* pp = pbuf + s * (ROWS * PROW) + rr * PROW;
            float sum = 0.0f;
            #pragma unroll
            for (int l = 0; l < LANES; l++) sum += pp[l];
            const float sc = apow[__popc(mb & ((1u << s) - 1u))];
            yb[(size_t)(ck * CHUNK + s) * NN + rb * ROWS + rr] = sc * sum;
        }
        // next top __syncthreads orders pbuf reads before overwrite
    }

    // ---- final W ----
    {
        float* wb = w_out + (size_t)b * NN * NN + (size_t)r0 * NN + cseg;
        #pragma unroll
        for (int i = 0; i < TR; i++) {
            ulonglong2 v0, v1;
            v0.x = w2[i][0]; v0.y = w2[i][1];
            v1.x = w2[i][2]; v1.y = w2[i][3];
            reinterpret_cast<ulonglong2*>(wb + i * NN)[0] = v0;
            reinterpret_cast<ulonglong2*>(wb + i * NN)[1] = v1;
        }
    }
}

extern "C" void kernel_launch(void* const* d_in, const int* in_sizes, int n_in,
                              void* d_out, int out_size) {
    const float* x      = (const float*)d_in[0];
    const float* w_init = (const float*)d_in[1];
    const float* alpha  = (const float*)d_in[2];
    const float* eta    = (const float*)d_in[3];
    const int*   mask   = (const int*)d_in[4];

    float* w_out = (float*)d_out;
    float* y_out = (float*)d_out + (size_t)BB * NN * NN;

    static bool attr_set = false;
    if (!attr_set) {
        cudaFuncSetAttribute(bdh_scan_kernel,
                             cudaFuncAttributeMaxDynamicSharedMemorySize, SM_BYTES);
        attr_set = true;
    }

    dim3 grid(BB, RBLK);
    bdh_scan_kernel<<<grid, THREADS, SM_BYTES>>>(x, w_init, alpha, eta, mask,
                                                 w_out, y_out);
}

// round 4
// speedup vs baseline: 3.9086x; 1.1907x over previous
#include <cuda_runtime.h>

#define BB 32
#define TT 1024
#define NN 128
#define RBLK 4                      // row-blocks per batch -> 128 CTAs
#define ROWS 32                     // rows per CTA
#define THREADS 128
#define TR 4                        // rows per thread
#define TC 8                        // cols per thread
#define LANES 16                    // lane-groups per row (128/TC)
#define CHUNK 32
#define NCHUNK (TT / CHUNK)

// pbuf layout in float4 units: [step][lane][q] with padding
#define PB_LANE 9                   // float4 stride per lane (pad 8->9)
#define PB_STEP 145                 // float4 stride per step (pad 144->145)

// smem (floats)
#define SM_XS    0
#define SM_PBUF  (2 * CHUNK * NN)                    // 8192
#define SM_APOW  (SM_PBUF + CHUNK * PB_STEP * 4)     // +18560
#define SM_MBITS (SM_APOW + CHUNK + 1)
#define SM_FLOATS (SM_MBITS + NCHUNK)
#define SM_BYTES (SM_FLOATS * 4)

typedef unsigned long long u64;

// ---------- packed f32x2 helpers ----------
__device__ __forceinline__ u64 pack2(float lo, float hi) {
    u64 r; asm("mov.b64 %0, {%1, %2};" : "=l"(r) : "f"(lo), "f"(hi)); return r;
}
__device__ __forceinline__ void unpack2(u64 v, float& lo, float& hi) {
    asm("mov.b64 {%0, %1}, %2;" : "=f"(lo), "=f"(hi) : "l"(v));
}
__device__ __forceinline__ u64 fma2(u64 a, u64 b, u64 c) {
    u64 d; asm("fma.rn.f32x2 %0, %1, %2, %3;" : "=l"(d) : "l"(a), "l"(b), "l"(c)); return d;
}
__device__ __forceinline__ u64 mul2(u64 a, u64 b) {
    u64 d; asm("mul.rn.f32x2 %0, %1, %2;" : "=l"(d) : "l"(a), "l"(b)); return d;
}
__device__ __forceinline__ u64 add2(u64 a, u64 b) {
    u64 d; asm("add.rn.f32x2 %0, %1, %2;" : "=l"(d) : "l"(a), "l"(b)); return d;
}

// ---------- cp.async ----------
__device__ __forceinline__ void cpasync16(void* s, const void* g) {
    unsigned saddr = (unsigned)__cvta_generic_to_shared(s);
    asm volatile("cp.async.cg.shared.global [%0], [%1], 16;" :: "r"(saddr), "l"(g));
}
__device__ __forceinline__ void load_chunk(float* dst, const float* src, int tid) {
    #pragma unroll
    for (int i = 0; i < 8; i++) {
        int off = (tid + i * THREADS) * 4;
        cpasync16(dst + off, src + off);
    }
}

__global__ __launch_bounds__(THREADS, 1)
void bdh_scan_kernel(const float* __restrict__ x,
                     const float* __restrict__ w_init,
                     const float* __restrict__ alpha_p,
                     const float* __restrict__ eta_p,
                     const int*   __restrict__ mask,
                     float* __restrict__ w_out,
                     float* __restrict__ y_out)
{
    extern __shared__ float smem[];
    float*    xs    = smem + SM_XS;
    float4*   pbuf  = reinterpret_cast<float4*>(smem + SM_PBUF);
    float*    apow  = smem + SM_APOW;
    unsigned* mbits = (unsigned*)(smem + SM_MBITS);

    const int b    = blockIdx.x;
    const int rb   = blockIdx.y;
    const int tid  = threadIdx.x;
    const int q    = tid / LANES;          // 0..7 row-group
    const int lane = tid % LANES;          // 0..15
    const int r0l  = q * TR;               // local first row
    const int r0   = rb * ROWS + r0l;      // global first row
    const int cseg = lane * TC;

    const float alpha = alpha_p[0];
    const float eta   = eta_p[0];
    const float inva  = 1.0f / alpha;

    // W tile: 4 rows x 8 cols as 16 packed f32x2
    u64 w2[TR][4];
    {
        const float* wb = w_init + (size_t)b * NN * NN + (size_t)r0 * NN + cseg;
        #pragma unroll
        for (int i = 0; i < TR; i++) {
            const ulonglong2* ws = reinterpret_cast<const ulonglong2*>(wb + i * NN);
            ulonglong2 v0 = ws[0], v1 = ws[1];
            w2[i][0] = v0.x; w2[i][1] = v0.y; w2[i][2] = v1.x; w2[i][3] = v1.y;
        }
    }

    // mask bitfields
    {
        const int l32 = tid & 31, wi = tid >> 5;
        for (int ckk = wi; ckk < NCHUNK; ckk += 4) {
            int m = mask[(size_t)b * TT + ckk * 32 + l32];
            unsigned bits = __ballot_sync(0xffffffffu, m != 0);
            if (l32 == 0) mbits[ckk] = bits;
        }
    }
    if (tid == 0) {
        float p = 1.0f;
        #pragma unroll
        for (int k = 0; k <= CHUNK; k++) { apow[k] = p; p *= alpha; }
    }

    const float* xb = x + (size_t)b * TT * NN;
    float* yb = y_out + (size_t)b * TT * NN;

    load_chunk(xs, xb, tid);
    asm volatile("cp.async.commit_group;");
    load_chunk(xs + CHUNK * NN, xb + CHUNK * NN, tid);
    asm volatile("cp.async.commit_group;");

    float c = 1.0f, ic = 1.0f;

    for (int ck = 0; ck < NCHUNK; ck++) {
        asm volatile("cp.async.wait_group 1;");
        __syncthreads();

        const float* xch = xs + (ck & 1) * (CHUNK * NN);
        const unsigned mb = mbits[ck];

        // ---- software-pipelined step loop ----
        ulonglong2 va = reinterpret_cast<const ulonglong2*>(xch + cseg)[0];
        ulonglong2 vb = reinterpret_cast<const ulonglong2*>(xch + cseg)[1];
        float4 xr = *reinterpret_cast<const float4*>(xch + rb * ROWS + r0l);

        #pragma unroll 8
        for (int tl = 0; tl < CHUNK; tl++) {
            const u64 xv0 = va.x, xv1 = va.y, xv2 = vb.x, xv3 = vb.y;
            const float4 xrc = xr;

            // prefetch next step's x (tl==31 over-reads into adjacent smem; unused)
            const float* xpn = xch + (tl + 1) * NN;
            va = reinterpret_cast<const ulonglong2*>(xpn + cseg)[0];
            vb = reinterpret_cast<const ulonglong2*>(xpn + cseg)[1];
            xr = *reinterpret_cast<const float4*>(xpn + rb * ROWS + r0l);

            // 4 dot chains, each: 4 packed ops -> unpack -> add
            float p[TR];
            #pragma unroll
            for (int i = 0; i < TR; i++) {
                u64 a = mul2(w2[i][0], xv0);
                a = fma2(w2[i][1], xv1, a);
                a = fma2(w2[i][2], xv2, a);
                a = fma2(w2[i][3], xv3, a);
                float lo, hi; unpack2(a, lo, hi);
                p[i] = lo + hi;
            }
            pbuf[tl * PB_STEP + lane * PB_LANE + q] =
                make_float4(p[0], p[1], p[2], p[3]);

            if ((mb >> tl) & 1u) {           // uniform branch
                c  *= alpha;
                ic *= inva;
                const float s = eta * ic;
                const u64 g0 = pack2(s * xrc.x, s * xrc.x);
                const u64 g1 = pack2(s * xrc.y, s * xrc.y);
                const u64 g2 = pack2(s * xrc.z, s * xrc.z);
                const u64 g3 = pack2(s * xrc.w, s * xrc.w);
                w2[0][0] = fma2(g0, xv0, w2[0][0]);
                w2[0][1] = fma2(g0, xv1, w2[0][1]);
                w2[0][2] = fma2(g0, xv2, w2[0][2]);
                w2[0][3] = fma2(g0, xv3, w2[0][3]);
                w2[1][0] = fma2(g1, xv0, w2[1][0]);
                w2[1][1] = fma2(g1, xv1, w2[1][1]);
                w2[1][2] = fma2(g1, xv2, w2[1][2]);
                w2[1][3] = fma2(g1, xv3, w2[1][3]);
                w2[2][0] = fma2(g2, xv0, w2[2][0]);
                w2[2][1] = fma2(g2, xv1, w2[2][1]);
                w2[2][2] = fma2(g2, xv2, w2[2][2]);
                w2[2][3] = fma2(g2, xv3, w2[2][3]);
                w2[3][0] = fma2(g3, xv0, w2[3][0]);
                w2[3][1] = fma2(g3, xv1, w2[3][1]);
                w2[3][2] = fma2(g3, xv2, w2[3][2]);
                w2[3][3] = fma2(g3, xv3, w2[3][3]);
            }
        }

        // fold decay into U
        if (c != 1.0f) {
            const u64 c2 = pack2(c, c);
            #pragma unroll
            for (int i = 0; i < TR; i++)
                #pragma unroll
                for (int k = 0; k < 4; k++) w2[i][k] = mul2(w2[i][k], c2);
            c = 1.0f; ic = 1.0f;
        }

        __syncthreads();

        const int nk = ck + 2;
        if (nk < NCHUNK)
            load_chunk(xs + (ck & 1) * (CHUNK * NN), xb + (size_t)nk * CHUNK * NN, tid);
        asm volatile("cp.async.commit_group;");

        // ---- bulk reduction: 256 tasks (s, q4) of 4 rows each ----
        #pragma unroll
        for (int o = 0; o < 2; o++) {
            const int idx = tid + o * THREADS;
            const int s  = idx >> 3;          // step in chunk
            const int qq = idx & 7;           // row-group
            const float4* pp = pbuf + s * PB_STEP + qq;
            ulonglong2 v = *reinterpret_cast<const ulonglong2*>(pp);
            u64 acc0 = v.x, acc1 = v.y;
            #pragma unroll
            for (int l = 1; l < LANES; l++) {
                v = *reinterpret_cast<const ulonglong2*>(pp + l * PB_LANE);
                acc0 = add2(acc0, v.x);
                acc1 = add2(acc1, v.y);
            }
            const float sc = apow[__popc(mb & ((1u << s) - 1u))];
            const u64 sc2 = pack2(sc, sc);
            ulonglong2 out;
            out.x = mul2(acc0, sc2);
            out.y = mul2(acc1, sc2);
            *reinterpret_cast<ulonglong2*>(
                yb + (size_t)(ck * CHUNK + s) * NN + rb * ROWS + qq * 4) = out;
        }
        // next top __syncthreads orders pbuf reads before overwrite
    }

    // final W
    {
        float* wb = w_out + (size_t)b * NN * NN + (size_t)r0 * NN + cseg;
        #pragma unroll
        for (int i = 0; i < TR; i++) {
            ulonglong2 v0, v1;
            v0.x = w2[i][0]; v0.y = w2[i][1];
            v1.x = w2[i][2]; v1.y = w2[i][3];
            reinterpret_cast<ulonglong2*>(wb + i * NN)[0] = v0;
            reinterpret_cast<ulonglong2*>(wb + i * NN)[1] = v1;
        }
    }
}

extern "C" void kernel_launch(void* const* d_in, const int* in_sizes, int n_in,
                              void* d_out, int out_size) {
    const float* x      = (const float*)d_in[0];
    const float* w_init = (const float*)d_in[1];
    const float* alpha  = (const float*)d_in[2];
    const float* eta    = (const float*)d_in[3];
    const int*   mask   = (const int*)d_in[4];

    float* w_out = (float*)d_out;
    float* y_out = (float*)d_out + (size_t)BB * NN * NN;

    static bool attr_set = false;
    if (!attr_set) {
        cudaFuncSetAttribute(bdh_scan_kernel,
                             cudaFuncAttributeMaxDynamicSharedMemorySize, SM_BYTES);
        attr_set = true;
    }

    dim3 grid(BB, RBLK);
    bdh_scan_kernel<<<grid, THREADS, SM_BYTES>>>(x, w_init, alpha, eta, mask,
                                                 w_out, y_out);
}

// round 5
// speedup vs baseline: 4.5687x; 1.1689x over previous
#include <cuda_runtime.h>

#define BB 32
#define TT 1024
#define NN 128
#define RBLK 4                      // row-blocks per batch -> 128 CTAs
#define ROWS 32                     // rows per CTA
#define THREADS 128
#define TR 4                        // rows per thread
#define TC 8                        // cols per thread
#define LANES 16                    // lane-groups per row (128/TC)
#define CHUNK 32
#define NCHUNK (TT / CHUNK)

// pbuf layout in float4 units: [step][lane][q] with padding
#define PB_LANE 9                   // float4 stride per lane (pad 8->9)
#define PB_STEP 145                 // float4 stride per step (pad 144->145)

// smem (floats)
#define SM_XS    0
#define SM_PBUF  (2 * CHUNK * NN)                    // 8192
#define SM_APOW  (SM_PBUF + CHUNK * PB_STEP * 4)     // +18560
#define SM_MBITS (SM_APOW + CHUNK + 1)
#define SM_FLOATS (SM_MBITS + NCHUNK)
#define SM_BYTES (SM_FLOATS * 4)

typedef unsigned long long u64;

// ---------- packed f32x2 helpers ----------
__device__ __forceinline__ u64 pack2(float lo, float hi) {
    u64 r; asm("mov.b64 %0, {%1, %2};" : "=l"(r) : "f"(lo), "f"(hi)); return r;
}
__device__ __forceinline__ void unpack2(u64 v, float& lo, float& hi) {
    asm("mov.b64 {%0, %1}, %2;" : "=f"(lo), "=f"(hi) : "l"(v));
}
__device__ __forceinline__ u64 fma2(u64 a, u64 b, u64 c) {
    u64 d; asm("fma.rn.f32x2 %0, %1, %2, %3;" : "=l"(d) : "l"(a), "l"(b), "l"(c)); return d;
}
__device__ __forceinline__ u64 mul2(u64 a, u64 b) {
    u64 d; asm("mul.rn.f32x2 %0, %1, %2;" : "=l"(d) : "l"(a), "l"(b)); return d;
}
__device__ __forceinline__ u64 add2(u64 a, u64 b) {
    u64 d; asm("add.rn.f32x2 %0, %1, %2;" : "=l"(d) : "l"(a), "l"(b)); return d;
}

// ---------- cp.async ----------
__device__ __forceinline__ void cpasync16(void* s, const void* g) {
    unsigned saddr = (unsigned)__cvta_generic_to_shared(s);
    asm volatile("cp.async.cg.shared.global [%0], [%1], 16;" :: "r"(saddr), "l"(g));
}
__device__ __forceinline__ void load_chunk(float* dst, const float* src, int tid) {
    #pragma unroll
    for (int i = 0; i < 8; i++) {
        int off = (tid + i * THREADS) * 4;
        cpasync16(dst + off, src + off);
    }
}

__global__ __launch_bounds__(THREADS, 1)
void bdh_scan_kernel(const float* __restrict__ x,
                     const float* __restrict__ w_init,
                     const float* __restrict__ alpha_p,
                     const float* __restrict__ eta_p,
                     const int*   __restrict__ mask,
                     float* __restrict__ w_out,
                     float* __restrict__ y_out)
{
    extern __shared__ float smem[];
    float*    xs    = smem + SM_XS;
    float4*   pbuf  = reinterpret_cast<float4*>(smem + SM_PBUF);
    float*    apow  = smem + SM_APOW;
    unsigned* mbits = (unsigned*)(smem + SM_MBITS);

    const int b    = blockIdx.x;
    const int rb   = blockIdx.y;
    const int tid  = threadIdx.x;
    const int q    = tid / LANES;          // 0..7 row-group
    const int lane = tid % LANES;          // 0..15
    const int r0l  = q * TR;               // local first row
    const int r0   = rb * ROWS + r0l;      // global first row
    const int cseg = lane * TC;

    const float alpha = alpha_p[0];
    const float eta   = eta_p[0];
    const float inva  = 1.0f / alpha;

    // W tile: 4 rows x 8 cols as 16 packed f32x2
    u64 w2[TR][4];
    {
        const float* wb = w_init + (size_t)b * NN * NN + (size_t)r0 * NN + cseg;
        #pragma unroll
        for (int i = 0; i < TR; i++) {
            const ulonglong2* ws = reinterpret_cast<const ulonglong2*>(wb + i * NN);
            ulonglong2 v0 = ws[0], v1 = ws[1];
            w2[i][0] = v0.x; w2[i][1] = v0.y; w2[i][2] = v1.x; w2[i][3] = v1.y;
        }
    }

    // mask bitfields
    {
        const int l32 = tid & 31, wi = tid >> 5;
        for (int ckk = wi; ckk < NCHUNK; ckk += 4) {
            int m = mask[(size_t)b * TT + ckk * 32 + l32];
            unsigned bits = __ballot_sync(0xffffffffu, m != 0);
            if (l32 == 0) mbits[ckk] = bits;
        }
    }
    if (tid == 0) {
        float p = 1.0f;
        #pragma unroll
        for (int k = 0; k <= CHUNK; k++) { apow[k] = p; p *= alpha; }
    }

    const float* xb = x + (size_t)b * TT * NN;
    float* yb = y_out + (size_t)b * TT * NN;

    load_chunk(xs, xb, tid);
    asm volatile("cp.async.commit_group;");
    load_chunk(xs + CHUNK * NN, xb + CHUNK * NN, tid);
    asm volatile("cp.async.commit_group;");

    float c = 1.0f, ic = 1.0f;

    for (int ck = 0; ck < NCHUNK; ck++) {
        asm volatile("cp.async.wait_group 1;");
        __syncthreads();

        const float* xch = xs + (ck & 1) * (CHUNK * NN);
        const unsigned mb = mbits[ck];

        // ---- software-pipelined, fully branch-free step loop ----
        ulonglong2 va = reinterpret_cast<const ulonglong2*>(xch + cseg)[0];
        ulonglong2 vb = reinterpret_cast<const ulonglong2*>(xch + cseg)[1];
        float4 xr = *reinterpret_cast<const float4*>(xch + rb * ROWS + r0l);

        #pragma unroll 16
        for (int tl = 0; tl < CHUNK; tl++) {
            const u64 xv0 = va.x, xv1 = va.y, xv2 = vb.x, xv3 = vb.y;
            const float4 xrc = xr;

            // prefetch next step's x (tl==31 over-reads adjacent smem; unused)
            const float* xpn = xch + (tl + 1) * NN;
            va = reinterpret_cast<const ulonglong2*>(xpn + cseg)[0];
            vb = reinterpret_cast<const ulonglong2*>(xpn + cseg)[1];
            xr = *reinterpret_cast<const float4*>(xpn + rb * ROWS + r0l);

            // 4 dot chains
            float p[TR];
            #pragma unroll
            for (int i = 0; i < TR; i++) {
                u64 a = mul2(w2[i][0], xv0);
                a = fma2(w2[i][1], xv1, a);
                a = fma2(w2[i][2], xv2, a);
                a = fma2(w2[i][3], xv3, a);
                float lo, hi; unpack2(a, lo, hi);
                p[i] = lo + hi;
            }
            pbuf[tl * PB_STEP + lane * PB_LANE + q] =
                make_float4(p[0], p[1], p[2], p[3]);

            // ---- branch-free masked update (s = 0 on unmasked steps) ----
            const bool m  = (mb >> tl) & 1u;
            const float ca = m ? alpha : 1.0f;
            const float ci = m ? inva  : 1.0f;
            c  *= ca;
            ic *= ci;
            const float s = m ? (eta * ic) : 0.0f;

            const float g0f = s * xrc.x, g1f = s * xrc.y;
            const float g2f = s * xrc.z, g3f = s * xrc.w;
            const u64 g0 = pack2(g0f, g0f);
            const u64 g1 = pack2(g1f, g1f);
            const u64 g2 = pack2(g2f, g2f);
            const u64 g3 = pack2(g3f, g3f);
            w2[0][0] = fma2(g0, xv0, w2[0][0]);
            w2[0][1] = fma2(g0, xv1, w2[0][1]);
            w2[0][2] = fma2(g0, xv2, w2[0][2]);
            w2[0][3] = fma2(g0, xv3, w2[0][3]);
            w2[1][0] = fma2(g1, xv0, w2[1][0]);
            w2[1][1] = fma2(g1, xv1, w2[1][1]);
            w2[1][2] = fma2(g1, xv2, w2[1][2]);
            w2[1][3] = fma2(g1, xv3, w2[1][3]);
            w2[2][0] = fma2(g2, xv0, w2[2][0]);
            w2[2][1] = fma2(g2, xv1, w2[2][1]);
            w2[2][2] = fma2(g2, xv2, w2[2][2]);
            w2[2][3] = fma2(g2, xv3, w2[2][3]);
            w2[3][0] = fma2(g3, xv0, w2[3][0]);
            w2[3][1] = fma2(g3, xv1, w2[3][1]);
            w2[3][2] = fma2(g3, xv2, w2[3][2]);
            w2[3][3] = fma2(g3, xv3, w2[3][3]);
        }

        // unconditional decay fold (c==1 only if whole chunk unmasked; exact)
        {
            const u64 c2 = pack2(c, c);
            #pragma unroll
            for (int i = 0; i < TR; i++)
                #pragma unroll
                for (int k = 0; k < 4; k++) w2[i][k] = mul2(w2[i][k], c2);
            c = 1.0f; ic = 1.0f;
        }

        __syncthreads();

        const int nk = ck + 2;
        if (nk < NCHUNK)
            load_chunk(xs + (ck & 1) * (CHUNK * NN), xb + (size_t)nk * CHUNK * NN, tid);
        asm volatile("cp.async.commit_group;");

        // ---- bulk reduction: 256 tasks (s, q4) of 4 rows each ----
        #pragma unroll
        for (int o = 0; o < 2; o++) {
            const int idx = tid + o * THREADS;
            const int s  = idx >> 3;          // step in chunk
            const int qq = idx & 7;           // row-group
            const float4* pp = pbuf + s * PB_STEP + qq;
            ulonglong2 v = *reinterpret_cast<const ulonglong2*>(pp);
            u64 acc0 = v.x, acc1 = v.y;
            #pragma unroll
            for (int l = 1; l < LANES; l++) {
                v = *reinterpret_cast<const ulonglong2*>(pp + l * PB_LANE);
                acc0 = add2(acc0, v.x);
                acc1 = add2(acc1, v.y);
            }
            const float sc = apow[__popc(mb & ((1u << s) - 1u))];
            const u64 sc2 = pack2(sc, sc);
            ulonglong2 out;
            out.x = mul2(acc0, sc2);
            out.y = mul2(acc1, sc2);
            *reinterpret_cast<ulonglong2*>(
                yb + (size_t)(ck * CHUNK + s) * NN + rb * ROWS + qq * 4) = out;
        }
        // next top __syncthreads orders pbuf reads before overwrite
    }

    // final W
    {
        float* wb = w_out + (size_t)b * NN * NN + (size_t)r0 * NN + cseg;
        #pragma unroll
        for (int i = 0; i < TR; i++) {
            ulonglong2 v0, v1;
            v0.x = w2[i][0]; v0.y = w2[i][1];
            v1.x = w2[i][2]; v1.y = w2[i][3];
            reinterpret_cast<ulonglong2*>(wb + i * NN)[0] = v0;
            reinterpret_cast<ulonglong2*>(wb + i * NN)[1] = v1;
        }
    }
}

extern "C" void kernel_launch(void* const* d_in, const int* in_sizes, int n_in,
                              void* d_out, int out_size) {
    const float* x      = (const float*)d_in[0];
    const float* w_init = (const float*)d_in[1];
    const float* alpha  = (const float*)d_in[2];
    const float* eta    = (const float*)d_in[3];
    const int*   mask   = (const int*)d_in[4];

    float* w_out = (float*)d_out;
    float* y_out = (float*)d_out + (size_t)BB * NN * NN;

    static bool attr_set = false;
    if (!attr_set) {
        cudaFuncSetAttribute(bdh_scan_kernel,
                             cudaFuncAttributeMaxDynamicSharedMemorySize, SM_BYTES);
        attr_set = true;
    }

    dim3 grid(BB, RBLK);
    bdh_scan_kernel<<<grid, THREADS, SM_BYTES>>>(x, w_init, alpha, eta, mask,
                                                 w_out, y_out);
}